// round 12
// baseline (speedup 1.0000x reference)
#include <cuda_runtime.h>
#include <cuda_fp16.h>
#include <cstdint>

#define MEM_DIM 1024
#define N_CHILD 16384

// GEMM tiling (fp16 operands)
#define BM 128
#define BN 64
#define KB 64                    // K per stage (halves) = 128 B per row
#define NSTAGES 3
#define STAGE_BYTES 24576        // A 128x128B (16 KB) + B 64x128B (8 KB)
#define B_OFF 16384
#define NUM_K 16                 // MEM_DIM / KB
#define GRID_X (MEM_DIM / BN)    // 16
#define GRID_Y (N_CHILD / BM)    // 128
#define TOTAL_CTAS (GRID_X * GRID_Y)

// ---------------- scratch (no cudaMalloc allowed) ----------------
__device__ float  g_iou[3 * MEM_DIM];                 // i, u, o
__device__ float  g_partial[MEM_DIM];
__device__ unsigned int g_ticket;
__device__ __half g_Ah[(size_t)N_CHILD * MEM_DIM];    // fp16 child_h (32 MB)
__device__ __half g_Wf[(size_t)MEM_DIM * MEM_DIM];    // fp16 W_fh    (2 MB)

// ---------------- helpers ----------------
__device__ __forceinline__ uint32_t smem_u32(const void* p) {
    uint32_t a;
    asm("{ .reg .u64 t; cvta.to.shared.u64 t, %1; cvt.u32.u64 %0, t; }" : "=r"(a) : "l"(p));
    return a;
}

__device__ __forceinline__ void cp16(uint32_t dst, const void* src) {
    asm volatile("cp.async.cg.shared.global [%0], [%1], 16;" :: "r"(dst), "l"(src));
}

__device__ __forceinline__ void ldsm_x4(uint32_t* r, uint32_t addr) {
    asm volatile("ldmatrix.sync.aligned.m8n8.x4.shared.b16 {%0,%1,%2,%3}, [%4];"
                 : "=r"(r[0]), "=r"(r[1]), "=r"(r[2]), "=r"(r[3]) : "r"(addr));
}

__device__ __forceinline__ void mma16816(float* d, const uint32_t* a, const uint32_t* b) {
    asm volatile(
        "mma.sync.aligned.m16n8k16.row.col.f32.f16.f16.f32 "
        "{%0,%1,%2,%3}, {%4,%5,%6,%7}, {%8,%9}, {%0,%1,%2,%3};"
        : "+f"(d[0]), "+f"(d[1]), "+f"(d[2]), "+f"(d[3])
        : "r"(a[0]), "r"(a[1]), "r"(a[2]), "r"(a[3]), "r"(b[0]), "r"(b[1]));
}

__device__ __forceinline__ uint32_t h2bits(__half2 v) {
    return *reinterpret_cast<uint32_t*>(&v);
}

// ---------------------------------------------------------------------------
// Kernel 0: fused prep — zero g_partial/g_ticket, convert child_h/W_fh to
// fp16, and compute the three GEMVs (i, u, o).
// Grid: 1024 x 256 (262144 threads; warps 0..3071 additionally do GEMV).
// ---------------------------------------------------------------------------
__global__ void prep_kernel(const float* __restrict__ h, const float* __restrict__ w,
                            const float* __restrict__ hs,
                            const float* __restrict__ W_ih, const float* __restrict__ b_ih,
                            const float* __restrict__ W_uh, const float* __restrict__ b_uh,
                            const float* __restrict__ W_oh, const float* __restrict__ b_oh) {
    const int gtid = blockIdx.x * blockDim.x + threadIdx.x;
    const int stride = gridDim.x * blockDim.x;

    if (gtid < MEM_DIM) g_partial[gtid] = 0.0f;
    if (gtid == 0) g_ticket = 0u;

    // ---- convert child_h: 8 floats -> uint4 store, exactly 8 iterations ----
    const float4* h4 = reinterpret_cast<const float4*>(h);
    uint4* a4 = reinterpret_cast<uint4*>(g_Ah);
    #pragma unroll 4
    for (int t = gtid; t < (N_CHILD * MEM_DIM) / 8; t += stride) {
        float4 v0 = h4[2 * t];
        float4 v1 = h4[2 * t + 1];
        uint4 o;
        o.x = h2bits(__floats2half2_rn(v0.x, v0.y));
        o.y = h2bits(__floats2half2_rn(v0.z, v0.w));
        o.z = h2bits(__floats2half2_rn(v1.x, v1.y));
        o.w = h2bits(__floats2half2_rn(v1.z, v1.w));
        a4[t] = o;
    }
    // ---- convert W_fh ----
    const float4* w4 = reinterpret_cast<const float4*>(w);
    uint4* b4 = reinterpret_cast<uint4*>(g_Wf);
    for (int t = gtid; t < (MEM_DIM * MEM_DIM) / 8; t += stride) {
        float4 v0 = w4[2 * t];
        float4 v1 = w4[2 * t + 1];
        uint4 o;
        o.x = h2bits(__floats2half2_rn(v0.x, v0.y));
        o.y = h2bits(__floats2half2_rn(v0.z, v0.w));
        o.z = h2bits(__floats2half2_rn(v1.x, v1.y));
        o.w = h2bits(__floats2half2_rn(v1.z, v1.w));
        b4[t] = o;
    }

    // ---- GEMVs: warps 0..3071, one output element each ----
    const int task = gtid >> 5;
    const int lane = gtid & 31;
    if (task >= 3 * MEM_DIM) return;
    const int mat = task >> 10;       // 0=i, 1=u, 2=o
    const int j   = task & 1023;

    const float* W = (mat == 0) ? W_ih : ((mat == 1) ? W_uh : W_oh);
    const float* b = (mat == 0) ? b_ih : ((mat == 1) ? b_uh : b_oh);

    const float4* Wr = reinterpret_cast<const float4*>(W + (size_t)j * MEM_DIM);
    const float4* hv = reinterpret_cast<const float4*>(hs);

    float sum = 0.0f;
    #pragma unroll 8
    for (int c = lane; c < MEM_DIM / 4; c += 32) {
        float4 wv = Wr[c];
        float4 h4v = hv[c];
        sum += wv.x * h4v.x + wv.y * h4v.y + wv.z * h4v.z + wv.w * h4v.w;
    }
    #pragma unroll
    for (int off = 16; off; off >>= 1)
        sum += __shfl_down_sync(0xffffffffu, sum, off);

    if (lane == 0) {
        float v = sum + b[j];
        float r = (mat == 1) ? tanhf(v) : (1.0f / (1.0f + __expf(-v)));
        g_iou[mat * MEM_DIM + j] = r;
    }
}

// ---------------------------------------------------------------------------
// Kernel 1: fp16 mma.sync fused fgate GEMM + sigmoid + child_c + reduction
// + (last CTA) final c/h combine written to out.
// CTA 128x64, 8 warps (4M x 2N), warp tile 32x32, ldmatrix fragment loads,
// 3-stage cp.async pipeline, ONE barrier per stage, 3 CTAs per SM.
// ---------------------------------------------------------------------------
__device__ __forceinline__ void load_stage(uint32_t sbase, int m0, int jb, int k0, int tid) {
    #pragma unroll
    for (int i = 0; i < 6; ++i) {
        const int t = tid + (i << 8);          // 0..1535 16B-chunks
        const int c = t & 7;                   // 16B chunk within 128B row
        if (t < 1024) {                        // A: 128 rows
            const int row = t >> 3;
            cp16(sbase + row * 128 + ((c ^ (row & 7)) << 4),
                 g_Ah + (size_t)(m0 + row) * MEM_DIM + k0 + c * 8);
        } else {                               // B: 64 rows
            const int row = (t - 1024) >> 3;
            cp16(sbase + B_OFF + row * 128 + ((c ^ (row & 7)) << 4),
                 g_Wf + (size_t)(jb + row) * MEM_DIM + k0 + c * 8);
        }
    }
}

__global__ void __launch_bounds__(256, 3)
fgate_mma(const float* __restrict__ child_c, const float* __restrict__ b_fh,
          float* __restrict__ out) {
    extern __shared__ char dsm[];
    __shared__ unsigned int s_ticket;

    const int tid = threadIdx.x;
    const int jb = blockIdx.x * BN;
    const int m0 = blockIdx.y * BM;
    const int warp = tid >> 5;
    const int lane = tid & 31;
    const int wm = warp >> 1;          // 0..3  (M, 32 rows each)
    const int wn = warp & 1;           // 0..1  (N, 32 cols each)
    const int rr = lane >> 2;          // 0..7
    const int kk = lane & 3;           // 0..3
    const int g  = lane >> 3;          // ldmatrix lane group 0..3
    const int lr = lane & 7;

    const uint32_t sbase = smem_u32(dsm);

    float acc[2][4][4];
    #pragma unroll
    for (int i = 0; i < 2; ++i)
        #pragma unroll
        for (int j = 0; j < 4; ++j)
            #pragma unroll
            for (int q = 0; q < 4; ++q) acc[i][j][q] = 0.0f;

    // prologue: stages 0, 1
    #pragma unroll
    for (int s = 0; s < NSTAGES - 1; ++s) {
        load_stage(sbase + s * STAGE_BYTES, m0, jb, s * KB, tid);
        asm volatile("cp.async.commit_group;" ::: "memory");
    }

    // per-lane ldmatrix bases
    const int arow0 = wm * 32 + (g & 1) * 8 + lr;
    const int brow0 = wn * 32 + (g >> 1) * 8 + lr;
    const int achunk_add = g >> 1;
    const int bchunk_add = g & 1;

    int buf = 0, nbuf = NSTAGES - 1;
    #pragma unroll 1
    for (int k = 0; k < NUM_K; ++k) {
        asm volatile("cp.async.wait_group 1;" ::: "memory");
        __syncthreads();   // single barrier per stage

        if (k + NSTAGES - 1 < NUM_K) {
            load_stage(sbase + nbuf * STAGE_BYTES, m0, jb, (k + NSTAGES - 1) * KB, tid);
        }
        asm volatile("cp.async.commit_group;" ::: "memory");
        nbuf = buf;

        const uint32_t sA = sbase + buf * STAGE_BYTES;
        const uint32_t sB = sA + B_OFF;
        buf = (buf + 1 == NSTAGES) ? 0 : buf + 1;

        #pragma unroll
        for (int ks = 0; ks < KB / 16; ++ks) {     // 4 k16 steps
            const int kc = 2 * ks;
            uint32_t a[2][4];
            #pragma unroll
            for (int i = 0; i < 2; ++i) {
                const int row = arow0 + i * 16;
                const int ch = (kc + achunk_add) ^ (row & 7);
                ldsm_x4(a[i], sA + row * 128 + (ch << 4));
            }
            uint32_t b[4][2];
            #pragma unroll
            for (int j = 0; j < 2; ++j) {
                const int row = brow0 + j * 16;
                const int ch = (kc + bchunk_add) ^ (row & 7);
                uint32_t r[4];
                ldsm_x4(r, sB + row * 128 + (ch << 4));
                b[2 * j][0] = r[0]; b[2 * j][1] = r[1];
                b[2 * j + 1][0] = r[2]; b[2 * j + 1][1] = r[3];
            }
            #pragma unroll
            for (int i = 0; i < 2; ++i)
                #pragma unroll
                for (int j = 0; j < 4; ++j)
                    mma16816(acc[i][j], a[i], b[j]);
        }
    }
    asm volatile("cp.async.wait_group 0;" ::: "memory");
    __syncthreads();

    // ---------------- epilogue ----------------
    float* F = (float*)dsm;            // 128 x 68 f32 = 34.8 KB
    const int FS = BN + 4;
    float* spart = (float*)(dsm + 36864);   // 4 x 64 partials
    #pragma unroll
    for (int i = 0; i < 2; ++i) {
        const int r0 = wm * 32 + i * 16 + rr;
        #pragma unroll
        for (int j = 0; j < 4; ++j) {
            const int c = wn * 32 + j * 8 + kk * 2;
            F[r0 * FS + c]           = acc[i][j][0];
            F[r0 * FS + c + 1]       = acc[i][j][1];
            F[(r0 + 8) * FS + c]     = acc[i][j][2];
            F[(r0 + 8) * FS + c + 1] = acc[i][j][3];
        }
    }
    __syncthreads();

    const int col = tid & 63;          // 0..63
    const int qq  = tid >> 6;          // 0..3, 32 rows each
    const float bias = __ldg(&b_fh[jb + col]);
    const float* crow = child_c + (size_t)(m0 + qq * 32) * MEM_DIM + jb + col;

    float s = 0.0f;
    #pragma unroll 4
    for (int m = 0; m < 32; ++m) {
        const float pre = F[(qq * 32 + m) * FS + col] + bias;
        const float f = 1.0f / (1.0f + __expf(-pre));
        s += f * crow[(size_t)m * MEM_DIM];
    }
    spart[qq * 64 + col] = s;
    __syncthreads();
    if (qq == 0) {
        float tot = spart[col] + spart[64 + col] + spart[128 + col] + spart[192 + col];
        atomicAdd(&g_partial[jb + col], tot);
        __threadfence();
    }
    __syncthreads();   // all atomics + fences done before taking the ticket

    // ---------------- last-CTA final combine ----------------
    if (tid == 0) s_ticket = atomicAdd(&g_ticket, 1u);
    __syncthreads();
    if (s_ticket == TOTAL_CTAS - 1) {
        __threadfence();
        #pragma unroll
        for (int r = 0; r < 4; ++r) {
            const int j = tid + r * 256;
            const float c = g_iou[j] * g_iou[MEM_DIM + j] + g_partial[j];
            out[j] = c;
            out[MEM_DIM + j] = g_iou[2 * MEM_DIM + j] * tanhf(c);
        }
    }
}

// ---------------------------------------------------------------------------
// Launch. Input order: child_c, child_h, child_h_sum,
// W_ih, b_ih, W_fh, b_fh, W_uh, b_uh, W_oh, b_oh.
// ---------------------------------------------------------------------------
extern "C" void kernel_launch(void* const* d_in, const int* in_sizes, int n_in,
                              void* d_out, int out_size) {
    (void)in_sizes; (void)n_in; (void)out_size;
    const float* child_c = (const float*)d_in[0];
    const float* child_h = (const float*)d_in[1];
    const float* hs      = (const float*)d_in[2];
    const float* W_ih    = (const float*)d_in[3];
    const float* b_ih    = (const float*)d_in[4];
    const float* W_fh    = (const float*)d_in[5];
    const float* b_fh    = (const float*)d_in[6];
    const float* W_uh    = (const float*)d_in[7];
    const float* b_uh    = (const float*)d_in[8];
    const float* W_oh    = (const float*)d_in[9];
    const float* b_oh    = (const float*)d_in[10];
    float* out = (float*)d_out;

    const int dyn_smem = NSTAGES * STAGE_BYTES;   // 72 KB -> 3 CTAs/SM
    static int attr_set = 0;
    if (!attr_set) {
        cudaFuncSetAttribute(fgate_mma, cudaFuncAttributeMaxDynamicSharedMemorySize, dyn_smem);
        attr_set = 1;
    }

    prep_kernel<<<1024, 256>>>(child_h, W_fh, hs,
                               W_ih, b_ih, W_uh, b_uh, W_oh, b_oh);

    dim3 grid(GRID_X, GRID_Y);   // (16, 128); x fastest for A reuse in L2
    fgate_mma<<<grid, 256, dyn_smem>>>(child_c, b_fh, out);
}

// round 13
// speedup vs baseline: 1.2903x; 1.2903x over previous
#include <cuda_runtime.h>
#include <cuda_fp16.h>
#include <cstdint>

#define MEM_DIM 1024
#define N_CHILD 16384

// GEMM tiling (fp16 operands)
#define BM 128
#define BN 64
#define KB 64                    // K per stage (halves) = 128 B per row
#define NSTAGES 2
#define STAGE_BYTES 24576        // A 128x128B (16 KB) + B 64x128B (8 KB)
#define B_OFF 16384
#define NUM_K 16                 // MEM_DIM / KB

// ---------------- scratch (no cudaMalloc allowed) ----------------
__device__ float  g_iou[3 * MEM_DIM];                 // i, u, o
__device__ float  g_partial[MEM_DIM];
__device__ __half g_Ah[(size_t)N_CHILD * MEM_DIM];    // fp16 child_h (32 MB)
__device__ __half g_Wf[(size_t)MEM_DIM * MEM_DIM];    // fp16 W_fh    (2 MB)

// ---------------- helpers ----------------
__device__ __forceinline__ uint32_t smem_u32(const void* p) {
    uint32_t a;
    asm("{ .reg .u64 t; cvta.to.shared.u64 t, %1; cvt.u32.u64 %0, t; }" : "=r"(a) : "l"(p));
    return a;
}

__device__ __forceinline__ void cp16(uint32_t dst, const void* src) {
    asm volatile("cp.async.cg.shared.global [%0], [%1], 16;" :: "r"(dst), "l"(src));
}

__device__ __forceinline__ void ldsm_x4(uint32_t* r, uint32_t addr) {
    asm volatile("ldmatrix.sync.aligned.m8n8.x4.shared.b16 {%0,%1,%2,%3}, [%4];"
                 : "=r"(r[0]), "=r"(r[1]), "=r"(r[2]), "=r"(r[3]) : "r"(addr));
}

__device__ __forceinline__ void mma16816(float* d, const uint32_t* a, const uint32_t* b) {
    asm volatile(
        "mma.sync.aligned.m16n8k16.row.col.f32.f16.f16.f32 "
        "{%0,%1,%2,%3}, {%4,%5,%6,%7}, {%8,%9}, {%0,%1,%2,%3};"
        : "+f"(d[0]), "+f"(d[1]), "+f"(d[2]), "+f"(d[3])
        : "r"(a[0]), "r"(a[1]), "r"(a[2]), "r"(a[3]), "r"(b[0]), "r"(b[1]));
}

__device__ __forceinline__ uint32_t h2bits(__half2 v) {
    return *reinterpret_cast<uint32_t*>(&v);
}

// ---------------------------------------------------------------------------
// Kernel 0: fused prep — zero g_partial, convert child_h/W_fh to fp16,
// and compute the three GEMVs (i, u, o).
// ---------------------------------------------------------------------------
__global__ void prep_kernel(const float* __restrict__ h, const float* __restrict__ w,
                            const float* __restrict__ hs,
                            const float* __restrict__ W_ih, const float* __restrict__ b_ih,
                            const float* __restrict__ W_uh, const float* __restrict__ b_uh,
                            const float* __restrict__ W_oh, const float* __restrict__ b_oh) {
    const int gtid = blockIdx.x * blockDim.x + threadIdx.x;
    const int stride = gridDim.x * blockDim.x;

    if (gtid < MEM_DIM) g_partial[gtid] = 0.0f;

    // ---- convert child_h: 8 floats -> uint4 store, exactly 8 iterations ----
    const float4* h4 = reinterpret_cast<const float4*>(h);
    uint4* a4 = reinterpret_cast<uint4*>(g_Ah);
    #pragma unroll 4
    for (int t = gtid; t < (N_CHILD * MEM_DIM) / 8; t += stride) {
        float4 v0 = h4[2 * t];
        float4 v1 = h4[2 * t + 1];
        uint4 o;
        o.x = h2bits(__floats2half2_rn(v0.x, v0.y));
        o.y = h2bits(__floats2half2_rn(v0.z, v0.w));
        o.z = h2bits(__floats2half2_rn(v1.x, v1.y));
        o.w = h2bits(__floats2half2_rn(v1.z, v1.w));
        a4[t] = o;
    }
    // ---- convert W_fh ----
    const float4* w4 = reinterpret_cast<const float4*>(w);
    uint4* b4 = reinterpret_cast<uint4*>(g_Wf);
    for (int t = gtid; t < (MEM_DIM * MEM_DIM) / 8; t += stride) {
        float4 v0 = w4[2 * t];
        float4 v1 = w4[2 * t + 1];
        uint4 o;
        o.x = h2bits(__floats2half2_rn(v0.x, v0.y));
        o.y = h2bits(__floats2half2_rn(v0.z, v0.w));
        o.z = h2bits(__floats2half2_rn(v1.x, v1.y));
        o.w = h2bits(__floats2half2_rn(v1.z, v1.w));
        b4[t] = o;
    }

    // ---- GEMVs: warps 0..3071, one output element each ----
    const int task = gtid >> 5;
    const int lane = gtid & 31;
    if (task >= 3 * MEM_DIM) return;
    const int mat = task >> 10;       // 0=i, 1=u, 2=o
    const int j   = task & 1023;

    const float* W = (mat == 0) ? W_ih : ((mat == 1) ? W_uh : W_oh);
    const float* b = (mat == 0) ? b_ih : ((mat == 1) ? b_uh : b_oh);

    const float4* Wr = reinterpret_cast<const float4*>(W + (size_t)j * MEM_DIM);
    const float4* hv = reinterpret_cast<const float4*>(hs);

    float sum = 0.0f;
    #pragma unroll 8
    for (int c = lane; c < MEM_DIM / 4; c += 32) {
        float4 wv = Wr[c];
        float4 h4v = hv[c];
        sum += wv.x * h4v.x + wv.y * h4v.y + wv.z * h4v.z + wv.w * h4v.w;
    }
    #pragma unroll
    for (int off = 16; off; off >>= 1)
        sum += __shfl_down_sync(0xffffffffu, sum, off);

    if (lane == 0) {
        float v = sum + b[j];
        float r = (mat == 1) ? tanhf(v) : (1.0f / (1.0f + __expf(-v)));
        g_iou[mat * MEM_DIM + j] = r;
    }
}

// ---------------------------------------------------------------------------
// Kernel 1: fp16 mma.sync fused fgate GEMM + sigmoid + child_c + reduction.
// CTA 128x64, 8 warps (4M x 2N), warp tile 32x32, ldmatrix fragment loads,
// 2-stage cp.async pipeline, ONE barrier per stage, 4 CTAs per SM.
// ---------------------------------------------------------------------------
__device__ __forceinline__ void load_stage(uint32_t sbase, int m0, int jb, int k0, int tid) {
    #pragma unroll
    for (int i = 0; i < 6; ++i) {
        const int t = tid + (i << 8);          // 0..1535 16B-chunks
        const int c = t & 7;                   // 16B chunk within 128B row
        if (t < 1024) {                        // A: 128 rows
            const int row = t >> 3;
            cp16(sbase + row * 128 + ((c ^ (row & 7)) << 4),
                 g_Ah + (size_t)(m0 + row) * MEM_DIM + k0 + c * 8);
        } else {                               // B: 64 rows
            const int row = (t - 1024) >> 3;
            cp16(sbase + B_OFF + row * 128 + ((c ^ (row & 7)) << 4),
                 g_Wf + (size_t)(jb + row) * MEM_DIM + k0 + c * 8);
        }
    }
}

__global__ void __launch_bounds__(256, 4)
fgate_mma(const float* __restrict__ child_c, const float* __restrict__ b_fh) {
    extern __shared__ char dsm[];

    const int tid = threadIdx.x;
    const int jb = blockIdx.x * BN;
    const int m0 = blockIdx.y * BM;
    const int warp = tid >> 5;
    const int lane = tid & 31;
    const int wm = warp >> 1;          // 0..3  (M, 32 rows each)
    const int wn = warp & 1;           // 0..1  (N, 32 cols each)
    const int rr = lane >> 2;          // 0..7
    const int kk = lane & 3;           // 0..3
    const int g  = lane >> 3;          // ldmatrix lane group 0..3
    const int lr = lane & 7;

    const uint32_t sbase = smem_u32(dsm);

    float acc[2][4][4];
    #pragma unroll
    for (int i = 0; i < 2; ++i)
        #pragma unroll
        for (int j = 0; j < 4; ++j)
            #pragma unroll
            for (int q = 0; q < 4; ++q) acc[i][j][q] = 0.0f;

    // prologue: stage 0
    load_stage(sbase, m0, jb, 0, tid);
    asm volatile("cp.async.commit_group;" ::: "memory");

    // per-lane ldmatrix bases
    const int arow0 = wm * 32 + (g & 1) * 8 + lr;
    const int brow0 = wn * 32 + (g >> 1) * 8 + lr;
    const int achunk_add = g >> 1;
    const int bchunk_add = g & 1;

    #pragma unroll 1
    for (int k = 0; k < NUM_K; ++k) {
        asm volatile("cp.async.wait_group 0;" ::: "memory");
        __syncthreads();   // stage k ready; buffer (k+1)&1 free (computed at k-1)

        if (k + 1 < NUM_K) {
            load_stage(sbase + ((k + 1) & 1) * STAGE_BYTES, m0, jb, (k + 1) * KB, tid);
        }
        asm volatile("cp.async.commit_group;" ::: "memory");

        const uint32_t sA = sbase + (k & 1) * STAGE_BYTES;
        const uint32_t sB = sA + B_OFF;

        #pragma unroll
        for (int ks = 0; ks < KB / 16; ++ks) {     // 4 k16 steps
            const int kc = 2 * ks;
            uint32_t a[2][4];
            #pragma unroll
            for (int i = 0; i < 2; ++i) {
                const int row = arow0 + i * 16;
                const int ch = (kc + achunk_add) ^ (row & 7);
                ldsm_x4(a[i], sA + row * 128 + (ch << 4));
            }
            uint32_t b[4][2];
            #pragma unroll
            for (int j = 0; j < 2; ++j) {
                const int row = brow0 + j * 16;
                const int ch = (kc + bchunk_add) ^ (row & 7);
                uint32_t r[4];
                ldsm_x4(r, sB + row * 128 + (ch << 4));
                b[2 * j][0] = r[0]; b[2 * j][1] = r[1];
                b[2 * j + 1][0] = r[2]; b[2 * j + 1][1] = r[3];
            }
            #pragma unroll
            for (int i = 0; i < 2; ++i)
                #pragma unroll
                for (int j = 0; j < 4; ++j)
                    mma16816(acc[i][j], a[i], b[j]);
        }
    }
    asm volatile("cp.async.wait_group 0;" ::: "memory");
    __syncthreads();

    // ---------------- epilogue ----------------
    float* F = (float*)dsm;            // 128 x 68 f32 = 34.8 KB (fits in 48 KB)
    const int FS = BN + 4;
    float* spart = (float*)(dsm + 36864);   // 4 x 64 partials
    #pragma unroll
    for (int i = 0; i < 2; ++i) {
        const int r0 = wm * 32 + i * 16 + rr;
        #pragma unroll
        for (int j = 0; j < 4; ++j) {
            const int c = wn * 32 + j * 8 + kk * 2;
            F[r0 * FS + c]           = acc[i][j][0];
            F[r0 * FS + c + 1]       = acc[i][j][1];
            F[(r0 + 8) * FS + c]     = acc[i][j][2];
            F[(r0 + 8) * FS + c + 1] = acc[i][j][3];
        }
    }
    __syncthreads();

    const int col = tid & 63;          // 0..63
    const int qq  = tid >> 6;          // 0..3, 32 rows each
    const float bias = __ldg(&b_fh[jb + col]);
    const float* crow = child_c + (size_t)(m0 + qq * 32) * MEM_DIM + jb + col;

    float s = 0.0f;
    #pragma unroll 4
    for (int m = 0; m < 32; ++m) {
        const float pre = F[(qq * 32 + m) * FS + col] + bias;
        const float f = 1.0f / (1.0f + __expf(-pre));
        s += f * crow[(size_t)m * MEM_DIM];
    }
    spart[qq * 64 + col] = s;
    __syncthreads();
    if (qq == 0) {
        float tot = spart[col] + spart[64 + col] + spart[128 + col] + spart[192 + col];
        atomicAdd(&g_partial[jb + col], tot);
    }
}

// ---------------------------------------------------------------------------
// Kernel 3: final combine. out[0:1024)=c, out[1024:2048)=h.
// ---------------------------------------------------------------------------
__global__ void finish_kernel(float* __restrict__ out) {
    const int j = blockIdx.x * blockDim.x + threadIdx.x;
    if (j < MEM_DIM) {
        float c = g_iou[j] * g_iou[MEM_DIM + j] + g_partial[j];
        out[j] = c;
        out[MEM_DIM + j] = g_iou[2 * MEM_DIM + j] * tanhf(c);
    }
}

// ---------------------------------------------------------------------------
// Launch. Input order: child_c, child_h, child_h_sum,
// W_ih, b_ih, W_fh, b_fh, W_uh, b_uh, W_oh, b_oh.
// ---------------------------------------------------------------------------
extern "C" void kernel_launch(void* const* d_in, const int* in_sizes, int n_in,
                              void* d_out, int out_size) {
    (void)in_sizes; (void)n_in; (void)out_size;
    const float* child_c = (const float*)d_in[0];
    const float* child_h = (const float*)d_in[1];
    const float* hs      = (const float*)d_in[2];
    const float* W_ih    = (const float*)d_in[3];
    const float* b_ih    = (const float*)d_in[4];
    const float* W_fh    = (const float*)d_in[5];
    const float* b_fh    = (const float*)d_in[6];
    const float* W_uh    = (const float*)d_in[7];
    const float* b_uh    = (const float*)d_in[8];
    const float* W_oh    = (const float*)d_in[9];
    const float* b_oh    = (const float*)d_in[10];
    float* out = (float*)d_out;

    const int dyn_smem = NSTAGES * STAGE_BYTES;   // 48 KB -> 4 CTAs/SM
    static int attr_set = 0;
    if (!attr_set) {
        cudaFuncSetAttribute(fgate_mma, cudaFuncAttributeMaxDynamicSharedMemorySize, dyn_smem);
        attr_set = 1;
    }

    prep_kernel<<<1024, 256>>>(child_h, W_fh, hs,
                               W_ih, b_ih, W_uh, b_uh, W_oh, b_oh);

    dim3 grid(MEM_DIM / BN, N_CHILD / BM);   // (16, 128); x fastest for A reuse in L2
    fgate_mma<<<grid, 256, dyn_smem>>>(child_c, b_fh);

    finish_kernel<<<2, 512>>>(out);
}